// round 16
// baseline (speedup 1.0000x reference)
#include <cuda_runtime.h>
#include <cuda_bf16.h>

#define SDIM  1024
#define BATCH 256
#define NBLK  32
#define BPB   8            // batches per block
#define TPB   288          // 9 warps x 32 = 288 (batch, window-elem) pairs
#define FULLM 0xFFFFFFFFu

// Global packed accumulator:
//   bits [63:23] : loss sum, fixed point, quantum 2^-24 (total < 2^40 -> 41b field)
//   bits [22: 9] : valid count  (<= 9216 -> 14 bits)
//   bits [ 8: 0] : block arrivals (= 32  ->  9 bits)
// Field totals cannot carry across boundaries. One atomicAdd per block both
// accumulates and signals arrival; returned old value lets the last block
// finalize inline. Last block resets to 0 for the next graph replay.
#define SUM_SHIFT 23
#define CNT_SHIFT 9
#define SUM_QF    16777216.0f   // 2^24
#define SUM_QD    16777216.0    // 2^24

__device__ unsigned long long g_acc = 0ULL;

__global__ __launch_bounds__(TPB)
void loss_kernel(const float* __restrict__ yp,
                 const int*   __restrict__ gt,
                 float*       __restrict__ out)
{
    const int t    = threadIdx.x;
    const int lane = t & 31;
    const int warp = t >> 5;

    // per-warp partials: (warp_sum_q << 16) | warp_valid_count
    __shared__ unsigned long long spart[9];

    // ---- all loads issue immediately (full MLP, no cross-warp deps) ----
    const int lb = t / 36;            // 0..7  (local batch)
    const int k  = t - lb * 36;       // 0..35 (window element)
    const int b  = blockIdx.x * BPB + lb;

    const int2 g = __ldg((const int2*)(gt + 2 * b));

    // every warp redundantly loads all 256 gt pairs (128 int4) for S-sums
    const int4* g4 = (const int4*)gt;
    int4 gv[4];
#pragma unroll
    for (int i = 0; i < 4; i++)
        gv[i] = __ldg(&g4[lane + 32 * i]);

    const int p0 = g.x + k / 6 - 3;
    const int p1 = g.y + k % 6 - 3;
    const bool valid = (p0 >= 0) & (p0 < SDIM) & (p1 >= 0) & (p1 < SDIM);
    float yh = 0.5f;
    if (valid)
        yh = __ldg(&yp[(size_t)b * (SDIM * SDIM) + (size_t)p0 * SDIM + p1]);

    // ---- S0/S1/Q via per-lane u32 partials + REDUX (single-instr reduce) ----
    unsigned int s0 = 0, s1 = 0, q = 0;
#pragma unroll
    for (int i = 0; i < 4; i++) {
        const int4 v = gv[i];
        s0 += (unsigned int)(v.x + v.z);
        s1 += (unsigned int)(v.y + v.w);
        q  += (unsigned int)(v.x * v.x + v.y * v.y + v.z * v.z + v.w * v.w);
    }
    const long long S0 = (long long)__reduce_add_sync(FULLM, s0);
    const long long S1 = (long long)__reduce_add_sync(FULLM, s1);
    const long long Q  = (long long)__reduce_add_sync(FULLM, q);

    // ---- per-thread term ----
    unsigned int qtm = 0u;
    if (valid) {
        // sq = sum_{b'} ||pos - gt[b']||^2 (exact closed form)
        const long long sq =
            (long long)BATCH * ((long long)p0 * p0 + (long long)p1 * p1)
            - 2LL * ((long long)p0 * S0 + (long long)p1 * S1) + Q;
        const float y = expf(-(float)sq * 0.2f);
        const float d = yh - y;
        float tm;
        if (y == 1.0f) {
            tm = -logf(yh) * d * d;
        } else {
            const float om  = 1.0f - y;
            const float om2 = om * om;
            tm = -logf(1.0f - yh) * om2 * om2 * d * d;
        }
        qtm = (unsigned int)(tm * SUM_QF + 0.5f);   // tm in [0, ~4.61)
    }

    // ---- warp reduce: one REDUX + one ballot/popc ----
    const unsigned int wsum = __reduce_add_sync(FULLM, qtm);            // < 2^32
    const unsigned int wcnt = __popc(__ballot_sync(FULLM, valid));      // <= 32
    if (lane == 0)
        spart[warp] = ((unsigned long long)wsum << 16) | wcnt;

    __syncthreads();   // the only barrier

    if (t == 0) {
        unsigned long long acc = 0ULL;
#pragma unroll
        for (int w = 0; w < 9; w++)
            acc += spart[w];                       // fields can't carry
        const unsigned long long bsum = acc >> 16;           // block sum_q
        const unsigned long long bcnt = acc & 0xFFFFULL;     // block count

        const unsigned long long mine =
            (bsum << SUM_SHIFT) | (bcnt << CNT_SHIFT) | 1ULL;
        const unsigned long long old = atomicAdd(&g_acc, mine);

        if ((old & 0x1FFULL) == (unsigned long long)(NBLK - 1)) {
            const unsigned long long fin  = old + mine;
            const unsigned long long fsum = fin >> SUM_SHIFT;
            const unsigned long long fcnt = (fin >> CNT_SHIFT) & 0x3FFFULL;
            out[0] = (float)(((double)fsum / SUM_QD) / (double)fcnt);
            g_acc = 0ULL;   // reset for next graph replay
        }
    }
}

extern "C" void kernel_launch(void* const* d_in, const int* in_sizes, int n_in,
                              void* d_out, int out_size)
{
    const float* y_predict = (const float*)d_in[0];
    const int*   gt_pos    = (const int*)d_in[1];
    float*       out       = (float*)d_out;
    loss_kernel<<<NBLK, TPB>>>(y_predict, gt_pos, out);
}